// round 8
// baseline (speedup 1.0000x reference)
#include <cuda_runtime.h>
#include <math.h>

#define DIM 2048
#define HID 8192
#define MAX_LEN 8192
#define G 148
#define NT 1024
#define NW 32
#define TOTW (G * NW)          // 4736 warps
#define MAXI 2                 // ceil((MAX_LEN+1)/TOTW)

// ---------------- scratch ----------------
__device__ float g_qkv[3 * DIM];           // q | k | v
__device__ float g_psum[G];                // per-block sum of exp
__device__ float g_partial[G * DIM];       // per-block weighted V partials
__device__ float g_attn[DIM];
__device__ float g_x2[DIM];
__device__ float g_h[HID];
__device__ unsigned g_bar;                 // barrier arrival counter (self-resetting)
__device__ unsigned g_gen;                 // barrier generation (monotonic)

__device__ __forceinline__ float warp_red(float v) {
#pragma unroll
    for (int o = 16; o > 0; o >>= 1) v += __shfl_xor_sync(0xffffffffu, v, o);
    return v;
}

// generation-counter grid barrier (all G blocks co-resident; replay-safe)
__device__ __forceinline__ void grid_barrier() {
    __syncthreads();
    if (threadIdx.x == 0) {
        __threadfence();
        unsigned gen = g_gen;                       // read BEFORE arrival
        if (atomicAdd(&g_bar, 1u) == G - 1u) {
            g_bar = 0;
            __threadfence();
            atomicAdd(&g_gen, 1u);
        } else {
            while (atomicAdd(&g_gen, 0u) == gen) __nanosleep(32);
        }
        __threadfence();
    }
    __syncthreads();
}

__global__ void __launch_bounds__(NT, 1)
k_all(const float* __restrict__ x,      const float* __restrict__ cacheK,
      const float* __restrict__ cacheV, const float* __restrict__ anw,
      const float* __restrict__ qw,     const float* __restrict__ qb,
      const float* __restrict__ kw,     const float* __restrict__ kb,
      const float* __restrict__ vw,     const float* __restrict__ vb,
      const float* __restrict__ ow,     const float* __restrict__ ob,
      const float* __restrict__ mnw,
      const float* __restrict__ w1,     const float* __restrict__ b1,
      const float* __restrict__ w2,     const float* __restrict__ b2,
      const int*   __restrict__ posp,   float* __restrict__ out) {
    __shared__ float s_buf[HID];        // 32KB, reused per phase
    __shared__ float s_e[MAXI][NW];
    __shared__ float s_red[NW];
    __shared__ float s_part[NW];
    __shared__ float s_scalar;

    int tid = threadIdx.x, warp = tid >> 5, lane = tid & 31, bid = blockIdx.x;
    int gw = bid * NW + warp;
    int pos = *posp;
    float4* sb4 = reinterpret_cast<float4*>(s_buf);

    // ======== phase 1: rmsnorm(x) -> s_buf, then QKV GEMV (6144 rows) ========
    {
        float4 v = (tid < 512) ? reinterpret_cast<const float4*>(x)[tid]
                               : make_float4(0.f, 0.f, 0.f, 0.f);
        float ss = v.x*v.x + v.y*v.y + v.z*v.z + v.w*v.w;
        ss = warp_red(ss);
        if (lane == 0) s_red[warp] = ss;
        __syncthreads();
        if (warp == 0) {
            float t = warp_red(s_red[lane]);
            if (lane == 0) s_scalar = rsqrtf(t * (1.f / DIM) + 1e-6f);
        }
        __syncthreads();
        float inv = s_scalar;
        if (tid < 512) {
            float4 w = reinterpret_cast<const float4*>(anw)[tid];
            sb4[tid] = make_float4(v.x*inv*w.x, v.y*inv*w.y, v.z*inv*w.z, v.w*inv*w.w);
        }
        __syncthreads();
        for (int r = gw; r < 3 * DIM; r += TOTW) {
            int m = r >> 11, j = r & (DIM - 1);
            const float* W = (m == 0) ? qw : (m == 1) ? kw : vw;
            const float* B = (m == 0) ? qb : (m == 1) ? kb : vb;
            const float4* w4 = reinterpret_cast<const float4*>(W + (size_t)j * DIM);
            float acc = 0.f;
#pragma unroll 16
            for (int i = lane; i < DIM / 4; i += 32) {
                float4 a = w4[i], b = sb4[i];
                acc += a.x*b.x + a.y*b.y + a.z*b.z + a.w*b.w;
            }
            acc = warp_red(acc);
            if (lane == 0) g_qkv[r] = acc + B[j];
        }
    }
    grid_barrier();

    // ======== phase 2: attention scores->exp + per-block weighted-V partials ========
    {
        if (tid < 512) sb4[tid] = reinterpret_cast<const float4*>(g_qkv)[tid];  // q
        if (tid < MAXI * NW) ((float*)s_e)[tid] = 0.f;
        __syncthreads();
#pragma unroll
        for (int i = 0; i < MAXI; i++) {
            int r = bid * NW + warp + i * TOTW;
            if (r <= pos) {
                const float* krow = (r == pos) ? (g_qkv + DIM)
                                               : (cacheK + (size_t)r * DIM);
                const float4* k4 = reinterpret_cast<const float4*>(krow);
                float acc = 0.f;
#pragma unroll 16
                for (int c = lane; c < DIM / 4; c += 32) {
                    float4 a = k4[c], b = sb4[c];
                    acc += a.x*b.x + a.y*b.y + a.z*b.z + a.w*b.w;
                }
                acc = warp_red(acc);
                if (lane == 0)
                    s_e[i][warp] = __expf(acc * 0.022097086912079608f);  // 1/sqrt(2048)
            }
        }
        __syncthreads();
        if (tid == 0) {
            float s = 0.f;
#pragma unroll
            for (int i = 0; i < MAXI * NW; i++) s += ((float*)s_e)[i];
            g_psum[bid] = s;
        }
        // each thread owns dims 2*tid, 2*tid+1
        float2 acc = make_float2(0.f, 0.f);
#pragma unroll
        for (int i = 0; i < MAXI; i++) {
#pragma unroll
            for (int w = 0; w < NW; w++) {
                int r = bid * NW + w + i * TOTW;
                if (r <= pos) {
                    float p = s_e[i][w];
                    const float2* v2 = (r == pos)
                        ? reinterpret_cast<const float2*>(g_qkv + 2 * DIM)
                        : reinterpret_cast<const float2*>(cacheV + (size_t)r * DIM);
                    float2 a = v2[tid];
                    acc.x += p * a.x;
                    acc.y += p * a.y;
                }
            }
        }
        reinterpret_cast<float2*>(g_partial + (size_t)bid * DIM)[tid] = acc;
    }
    grid_barrier();

    // ======== phase 3: reduce 148 partials + 1/Z (blocks 0..63, warp per dim) ========
    if (bid < 64) {
        float z = (tid < G) ? g_psum[tid] : 0.f;
        z = warp_red(z);
        if (lane == 0) s_red[warp] = z;
        __syncthreads();
        if (warp == 0) {
            float t = warp_red(s_red[lane]);
            if (lane == 0) s_scalar = 1.f / t;
        }
        __syncthreads();
        float invZ = s_scalar;
        int d = bid * NW + warp;           // 0..2047
        float acc = 0.f;
#pragma unroll
        for (int j = 0; j < 5; j++) {
            int k = lane + 32 * j;
            if (k < G) acc += g_partial[(size_t)k * DIM + d];
        }
        acc = warp_red(acc);
        if (lane == 0) g_attn[d] = acc * invZ;
    }
    grid_barrier();

    // ======== phase 4: o-proj + residual (2 warps/row, rows 0..2047) ========
    {
        if (tid < 512) sb4[tid] = reinterpret_cast<const float4*>(g_attn)[tid];
        __syncthreads();
        if (gw < 2 * DIM) {
            int row = gw >> 1, half = gw & 1;
            const float4* w4 = reinterpret_cast<const float4*>(ow + (size_t)row * DIM);
            float acc = 0.f;
            int base = half * 256;
#pragma unroll 8
            for (int i = base + lane; i < base + 256; i += 32) {
                float4 a = w4[i], b = sb4[i];
                acc += a.x*b.x + a.y*b.y + a.z*b.z + a.w*b.w;
            }
            acc = warp_red(acc);
            if (lane == 0) s_part[warp] = acc;
        }
        __syncthreads();
        if (gw < 2 * DIM && (warp & 1) == 0 && lane == 0) {
            int row = gw >> 1;
            g_x2[row] = x[row] + s_part[warp] + s_part[warp + 1] + ob[row];
        }
    }
    grid_barrier();

    // ======== phase 5: rmsnorm(g_x2) + fc1 + exact GELU (8192 rows) ========
    {
        float4 v = (tid < 512) ? reinterpret_cast<const float4*>(g_x2)[tid]
                               : make_float4(0.f, 0.f, 0.f, 0.f);
        float ss = v.x*v.x + v.y*v.y + v.z*v.z + v.w*v.w;
        ss = warp_red(ss);
        if (lane == 0) s_red[warp] = ss;
        __syncthreads();
        if (warp == 0) {
            float t = warp_red(s_red[lane]);
            if (lane == 0) s_scalar = rsqrtf(t * (1.f / DIM) + 1e-6f);
        }
        __syncthreads();
        float inv = s_scalar;
        if (tid < 512) {
            float4 w = reinterpret_cast<const float4*>(mnw)[tid];
            sb4[tid] = make_float4(v.x*inv*w.x, v.y*inv*w.y, v.z*inv*w.z, v.w*inv*w.w);
        }
        __syncthreads();
        for (int r = gw; r < HID; r += TOTW) {
            const float4* w4 = reinterpret_cast<const float4*>(w1 + (size_t)r * DIM);
            float acc = 0.f;
#pragma unroll 16
            for (int i = lane; i < DIM / 4; i += 32) {
                float4 a = w4[i], b = sb4[i];
                acc += a.x*b.x + a.y*b.y + a.z*b.z + a.w*b.w;
            }
            acc = warp_red(acc);
            if (lane == 0) {
                float u = acc + b1[r];
                g_h[r] = 0.5f * u * (1.f + erff(u * 0.70710678118654752f));
            }
        }
    }
    grid_barrier();

    // ======== phase 6: fc2 + residual -> out (2 warps/row, rows 0..2047) ========
    {
        sb4[tid]        = reinterpret_cast<const float4*>(g_h)[tid];
        sb4[tid + 1024] = reinterpret_cast<const float4*>(g_h)[tid + 1024];
        __syncthreads();
        if (gw < 2 * DIM) {
            int row = gw >> 1, half = gw & 1;
            const float4* w4 = reinterpret_cast<const float4*>(w2 + (size_t)row * HID);
            float acc = 0.f;
            int base = half * 1024;
#pragma unroll 8
            for (int i = base + lane; i < base + 1024; i += 32) {
                float4 a = w4[i], b = sb4[i];
                acc += a.x*b.x + a.y*b.y + a.z*b.z + a.w*b.w;
            }
            acc = warp_red(acc);
            if (lane == 0) s_part[warp] = acc;
        }
        __syncthreads();
        if (gw < 2 * DIM && (warp & 1) == 0 && lane == 0) {
            int row = gw >> 1;
            out[row] = g_x2[row] + s_part[warp] + s_part[warp + 1] + b2[row];
        }
    }
}

// ---------------- launch ----------------
extern "C" void kernel_launch(void* const* d_in, const int* in_sizes, int n_in,
                              void* d_out, int out_size) {
    const float* x      = (const float*)d_in[0];
    const float* cacheK = (const float*)d_in[1];
    const float* cacheV = (const float*)d_in[2];
    const float* anw    = (const float*)d_in[3];
    const float* qw     = (const float*)d_in[4];
    const float* qb     = (const float*)d_in[5];
    const float* kw     = (const float*)d_in[6];
    const float* kb     = (const float*)d_in[7];
    const float* vw     = (const float*)d_in[8];
    const float* vb     = (const float*)d_in[9];
    const float* ow     = (const float*)d_in[10];
    const float* ob     = (const float*)d_in[11];
    const float* mnw    = (const float*)d_in[12];
    const float* w1     = (const float*)d_in[13];
    const float* b1     = (const float*)d_in[14];
    const float* w2     = (const float*)d_in[15];
    const float* b2     = (const float*)d_in[16];
    const int*   posp   = (const int*)d_in[17];
    float* out = (float*)d_out;

    k_all<<<G, NT>>>(x, cacheK, cacheV, anw, qw, qb, kw, kb, vw, vb,
                     ow, ob, mnw, w1, b1, w2, b2, posp, out);
}

// round 10
// speedup vs baseline: 1.3878x; 1.3878x over previous
#include <cuda_runtime.h>
#include <math.h>

#define DIM 2048
#define HID 8192
#define MAX_LEN 8192
#define NSPLIT 128
#define NSB ((MAX_LEN + 8) / 8)   // 1025 score blocks (8 rows each)

// ---------------- scratch ----------------
__device__ float g_qkv[3 * DIM];            // q | k | v
__device__ float g_probs[MAX_LEN + 1];      // unnormalized exp(score)
__device__ float g_psum[NSB];               // per-block partial sums of exp
__device__ float g_invZ;                    // 1/sum(exp)
__device__ unsigned g_cnt;                  // last-block counter (self-resetting)
__device__ float g_partial[NSPLIT * DIM];
__device__ float g_attn[DIM];               // normalized attention output
__device__ float g_x2[DIM];                 // x + attn@oW + ob
__device__ float g_h[HID];                  // gelu(fc1)

__device__ __forceinline__ float warp_red(float v) {
#pragma unroll
    for (int o = 16; o > 0; o >>= 1) v += __shfl_xor_sync(0xffffffffu, v, o);
    return v;
}

// ---------------- kernel 1: fused rmsnorm + QKV GEMV (2 warps/row, 1536 blocks) ----------------
__global__ void k_qkv(const float* __restrict__ x, const float* __restrict__ anw,
                      const float* __restrict__ qw, const float* __restrict__ qb,
                      const float* __restrict__ kw, const float* __restrict__ kb,
                      const float* __restrict__ vw, const float* __restrict__ vb) {
    __shared__ float s_xn[DIM];
    __shared__ float s_red[8];
    __shared__ float s_part[4][2];
    __shared__ float s_inv;
    int tid = threadIdx.x, warp = tid >> 5, lane = tid & 31;

    const float4* x4 = reinterpret_cast<const float4*>(x);
    float4 v0 = x4[tid], v1 = x4[tid + 256];
    float ss = v0.x*v0.x + v0.y*v0.y + v0.z*v0.z + v0.w*v0.w
             + v1.x*v1.x + v1.y*v1.y + v1.z*v1.z + v1.w*v1.w;
    ss = warp_red(ss);
    if (lane == 0) s_red[warp] = ss;
    __syncthreads();
    if (tid == 0) {
        float t = 0.f;
#pragma unroll
        for (int i = 0; i < 8; i++) t += s_red[i];
        s_inv = rsqrtf(t * (1.f / DIM) + 1e-6f);
    }
    __syncthreads();
    float inv = s_inv;
    const float4* a4 = reinterpret_cast<const float4*>(anw);
    float4 n0 = a4[tid], n1 = a4[tid + 256];
    float4* sx4 = reinterpret_cast<float4*>(s_xn);
    sx4[tid]       = make_float4(v0.x*inv*n0.x, v0.y*inv*n0.y, v0.z*inv*n0.z, v0.w*inv*n0.w);
    sx4[tid + 256] = make_float4(v1.x*inv*n1.x, v1.y*inv*n1.y, v1.z*inv*n1.z, v1.w*inv*n1.w);
    __syncthreads();

    int rl = warp >> 1, half = warp & 1;
    int r = blockIdx.x * 4 + rl;            // 0..6143
    int m = r >> 11, j = r & (DIM - 1);
    const float* W = (m == 0) ? qw : (m == 1) ? kw : vw;
    const float4* w4 = reinterpret_cast<const float4*>(W + (size_t)j * DIM);
    float acc = 0.f;
    int base = half * 256;
#pragma unroll 8
    for (int i = base + lane; i < base + 256; i += 32) {
        float4 a = w4[i], b = sx4[i];
        acc += a.x*b.x + a.y*b.y + a.z*b.z + a.w*b.w;
    }
    acc = warp_red(acc);
    if (lane == 0) s_part[rl][half] = acc;
    __syncthreads();
    if (tid < 4) {
        int rr = blockIdx.x * 4 + tid;
        int mm = rr >> 11, jj = rr & (DIM - 1);
        const float* B = (mm == 0) ? qb : (mm == 1) ? kb : vb;
        g_qkv[rr] = s_part[tid][0] + s_part[tid][1] + B[jj];
    }
}

// ---------------- kernel 2: scores -> exp, last block computes 1/Z ----------------
__global__ void k_scores(const float* __restrict__ cacheK,
                         const int* __restrict__ posp) {
    __shared__ float s_q[DIM];
    __shared__ float s_e[8];
    __shared__ bool s_last;
    int pos = *posp;
    int tid = threadIdx.x, warp = tid >> 5, lane = tid & 31;
    float4* sq4 = reinterpret_cast<float4*>(s_q);
    const float4* q4 = reinterpret_cast<const float4*>(g_qkv);
    sq4[tid] = q4[tid];
    sq4[tid + 256] = q4[tid + 256];
    if (tid < 8) s_e[tid] = 0.f;
    __syncthreads();

    int row = blockIdx.x * 8 + warp;
    if (row <= pos) {
        const float* krow = (row == pos) ? (g_qkv + DIM)
                                         : (cacheK + (size_t)row * DIM);
        const float4* k4 = reinterpret_cast<const float4*>(krow);
        float acc = 0.f;
#pragma unroll 8
        for (int i = lane; i < DIM / 4; i += 32) {
            float4 a = k4[i], b = sq4[i];
            acc += a.x*b.x + a.y*b.y + a.z*b.z + a.w*b.w;
        }
        acc = warp_red(acc);
        if (lane == 0) {
            float e = __expf(acc * 0.022097086912079608f);  // 1/sqrt(2048)
            g_probs[row] = e;
            s_e[warp] = e;
        }
    }
    __syncthreads();
    if (tid == 0) {
        float s = 0.f;
#pragma unroll
        for (int i = 0; i < 8; i++) s += s_e[i];
        g_psum[blockIdx.x] = s;
        __threadfence();
        unsigned old = atomicAdd(&g_cnt, 1u);
        s_last = (old == (unsigned)(gridDim.x - 1));
    }
    __syncthreads();
    if (s_last) {
        __threadfence();
        float z = 0.f;
        for (int i = tid; i < NSB; i += 256) z += g_psum[i];
        s_q[tid] = z;
        __syncthreads();
        for (int st = 128; st > 0; st >>= 1) {
            if (tid < st) s_q[tid] += s_q[tid + st];
            __syncthreads();
        }
        if (tid == 0) {
            g_invZ = 1.f / s_q[0];
            g_cnt = 0;                       // reset for next graph replay
        }
    }
}

// ---------------- kernel 3: probs @ V, split-K (1024 blocks) ----------------
__global__ void k_attnv(const float* __restrict__ cacheV,
                        const int* __restrict__ posp) {
    int pos = *posp;
    int d = blockIdx.x * 256 + threadIdx.x;
    int s = blockIdx.y;
    float a0 = 0.f, a1 = 0.f, a2 = 0.f, a3 = 0.f;
    int i = s;
    for (; i + 3 * NSPLIT < pos; i += 4 * NSPLIT) {
        a0 += g_probs[i]              * cacheV[(size_t)i * DIM + d];
        a1 += g_probs[i + NSPLIT]     * cacheV[(size_t)(i + NSPLIT) * DIM + d];
        a2 += g_probs[i + 2 * NSPLIT] * cacheV[(size_t)(i + 2 * NSPLIT) * DIM + d];
        a3 += g_probs[i + 3 * NSPLIT] * cacheV[(size_t)(i + 3 * NSPLIT) * DIM + d];
    }
    for (; i < pos; i += NSPLIT)
        a0 += g_probs[i] * cacheV[(size_t)i * DIM + d];
    if (s == (pos & (NSPLIT - 1)))
        a0 += g_probs[pos] * g_qkv[2 * DIM + d];
    g_partial[(size_t)s * DIM + d] = (a0 + a1) + (a2 + a3);
}

// ---------------- kernel 4: reduce 128 partials (16 thr/dim) + 1/Z ----------------
__global__ void k_attnv_reduce() {
    int tid = threadIdx.x;
    int d = blockIdx.x * 16 + (tid >> 4);
    int q = tid & 15;
    float acc = 0.f;
#pragma unroll
    for (int k = 0; k < NSPLIT / 16; k++)
        acc += g_partial[(size_t)(q + 16 * k) * DIM + d];
    acc += __shfl_xor_sync(0xffffffffu, acc, 1);
    acc += __shfl_xor_sync(0xffffffffu, acc, 2);
    acc += __shfl_xor_sync(0xffffffffu, acc, 4);
    acc += __shfl_xor_sync(0xffffffffu, acc, 8);
    if (q == 0) g_attn[d] = acc * g_invZ;
}

// ---------------- kernel 5: o-proj + residual (4 warps/row, 1024 blocks) ----------------
__global__ void k_oproj(const float* __restrict__ ow, const float* __restrict__ ob,
                        const float* __restrict__ x) {
    __shared__ float s_a[DIM];
    __shared__ float s_part[2][4];
    int tid = threadIdx.x, warp = tid >> 5, lane = tid & 31;
    float4* sa4 = reinterpret_cast<float4*>(s_a);
    const float4* g4 = reinterpret_cast<const float4*>(g_attn);
    sa4[tid] = g4[tid];
    sa4[tid + 256] = g4[tid + 256];
    __syncthreads();

    int rl = warp >> 2, qtr = warp & 3;
    int row = blockIdx.x * 2 + rl;
    const float4* w4 = reinterpret_cast<const float4*>(ow + (size_t)row * DIM);
    float acc = 0.f;
    int base = qtr * 128;
#pragma unroll 4
    for (int i = base + lane; i < base + 128; i += 32) {
        float4 a = w4[i], b = sa4[i];
        acc += a.x*b.x + a.y*b.y + a.z*b.z + a.w*b.w;
    }
    acc = warp_red(acc);
    if (lane == 0) s_part[rl][qtr] = acc;
    __syncthreads();
    if (tid < 2) {
        int r = blockIdx.x * 2 + tid;
        g_x2[r] = x[r] + s_part[tid][0] + s_part[tid][1]
                       + s_part[tid][2] + s_part[tid][3] + ob[r];
    }
}

// ---------------- kernel 6: rmsnorm + fc1 + exact GELU (2 warps/row, 2048 blocks) ----------------
__global__ void k_fc1(const float* __restrict__ mnw,
                      const float* __restrict__ w1, const float* __restrict__ b1) {
    __shared__ float s_xn[DIM];
    __shared__ float s_red[8];
    __shared__ float s_part[4][2];
    __shared__ float s_inv;
    int tid = threadIdx.x, warp = tid >> 5, lane = tid & 31;

    const float4* x4 = reinterpret_cast<const float4*>(g_x2);
    float4 v0 = x4[tid], v1 = x4[tid + 256];
    float ss = v0.x*v0.x + v0.y*v0.y + v0.z*v0.z + v0.w*v0.w
             + v1.x*v1.x + v1.y*v1.y + v1.z*v1.z + v1.w*v1.w;
    ss = warp_red(ss);
    if (lane == 0) s_red[warp] = ss;
    __syncthreads();
    if (tid == 0) {
        float t = 0.f;
#pragma unroll
        for (int i = 0; i < 8; i++) t += s_red[i];
        s_inv = rsqrtf(t * (1.f / DIM) + 1e-6f);
    }
    __syncthreads();
    float inv = s_inv;
    const float4* m4 = reinterpret_cast<const float4*>(mnw);
    float4 n0 = m4[tid], n1 = m4[tid + 256];
    float4* sx4 = reinterpret_cast<float4*>(s_xn);
    sx4[tid]       = make_float4(v0.x*inv*n0.x, v0.y*inv*n0.y, v0.z*inv*n0.z, v0.w*inv*n0.w);
    sx4[tid + 256] = make_float4(v1.x*inv*n1.x, v1.y*inv*n1.y, v1.z*inv*n1.z, v1.w*inv*n1.w);
    __syncthreads();

    int rl = warp >> 1, half = warp & 1;
    int row = blockIdx.x * 4 + rl;          // 0..8191
    const float4* w4 = reinterpret_cast<const float4*>(w1 + (size_t)row * DIM);
    float acc = 0.f;
    int base = half * 256;
#pragma unroll 8
    for (int i = base + lane; i < base + 256; i += 32) {
        float4 a = w4[i], b = sx4[i];
        acc += a.x*b.x + a.y*b.y + a.z*b.z + a.w*b.w;
    }
    acc = warp_red(acc);
    if (lane == 0) s_part[rl][half] = acc;
    __syncthreads();
    if (tid < 4) {
        int r = blockIdx.x * 4 + tid;
        float u = s_part[tid][0] + s_part[tid][1] + b1[r];
        g_h[r] = 0.5f * u * (1.f + erff(u * 0.70710678118654752f));
    }
}

// ---------------- kernel 7: fc2 + residual -> out (4 warps/row, 1024 blocks) ----------------
__global__ void k_fc2(const float* __restrict__ w2, const float* __restrict__ b2,
                      float* __restrict__ out) {
    __shared__ float s_h[HID];
    __shared__ float s_part[2][4];
    int tid = threadIdx.x, warp = tid >> 5, lane = tid & 31;
    float4* sh4 = reinterpret_cast<float4*>(s_h);
    const float4* h4 = reinterpret_cast<const float4*>(g_h);
#pragma unroll
    for (int i = 0; i < 8; i++) sh4[tid + 256 * i] = h4[tid + 256 * i];
    __syncthreads();

    int rl = warp >> 2, qtr = warp & 3;
    int row = blockIdx.x * 2 + rl;
    const float4* w4 = reinterpret_cast<const float4*>(w2 + (size_t)row * HID);
    float acc = 0.f;
    int base = qtr * 512;
#pragma unroll 8
    for (int i = base + lane; i < base + 512; i += 32) {
        float4 a = w4[i], b = sh4[i];
        acc += a.x*b.x + a.y*b.y + a.z*b.z + a.w*b.w;
    }
    acc = warp_red(acc);
    if (lane == 0) s_part[rl][qtr] = acc;
    __syncthreads();
    if (tid < 2) {
        int r = blockIdx.x * 2 + tid;
        out[r] = g_x2[r] + s_part[tid][0] + s_part[tid][1]
                         + s_part[tid][2] + s_part[tid][3] + b2[r];
    }
}

// ---------------- launch ----------------
extern "C" void kernel_launch(void* const* d_in, const int* in_sizes, int n_in,
                              void* d_out, int out_size) {
    const float* x      = (const float*)d_in[0];
    const float* cacheK = (const float*)d_in[1];
    const float* cacheV = (const float*)d_in[2];
    const float* anw    = (const float*)d_in[3];
    const float* qw     = (const float*)d_in[4];
    const float* qb     = (const float*)d_in[5];
    const float* kw     = (const float*)d_in[6];
    const float* kb     = (const float*)d_in[7];
    const float* vw     = (const float*)d_in[8];
    const float* vb     = (const float*)d_in[9];
    const float* ow     = (const float*)d_in[10];
    const float* ob     = (const float*)d_in[11];
    const float* mnw    = (const float*)d_in[12];
    const float* w1     = (const float*)d_in[13];
    const float* b1     = (const float*)d_in[14];
    const float* w2     = (const float*)d_in[15];
    const float* b2     = (const float*)d_in[16];
    const int*   posp   = (const int*)d_in[17];
    float* out = (float*)d_out;

    k_qkv<<<(3 * DIM) / 4, 256>>>(x, anw, qw, qb, kw, kb, vw, vb);
    k_scores<<<NSB, 256>>>(cacheK, posp);
    k_attnv<<<dim3(DIM / 256, NSPLIT), 256>>>(cacheV, posp);
    k_attnv_reduce<<<DIM / 16, 256>>>();
    k_oproj<<<DIM / 2, 256>>>(ow, ob, x);
    k_fc1<<<HID / 4, 256>>>(mnw, w1, b1);
    k_fc2<<<DIM / 2, 256>>>(w2, b2, out);
}

// round 12
// speedup vs baseline: 1.5951x; 1.1494x over previous
#include <cuda_runtime.h>
#include <math.h>

#define DIM 2048
#define HID 8192
#define MAX_LEN 8192
#define NSPLIT 64
#define NSB ((MAX_LEN + 16) / 16)  // 513 score blocks (16 rows each)

// ---------------- scratch ----------------
__device__ float g_qkv[3 * DIM];            // q | k | v
__device__ float g_probs[MAX_LEN + 1];      // unnormalized exp(score)
__device__ float g_psum[NSB];               // per-block partial sums of exp
__device__ float g_invZ;                    // 1/sum(exp)
__device__ unsigned g_cnt;                  // last-block counter (self-resetting)
__device__ float g_partial[NSPLIT * DIM];
__device__ float g_attn[DIM];               // normalized attention output
__device__ float g_x2[DIM];                 // x + attn@oW + ob
__device__ float g_h[HID];                  // gelu(fc1)

__device__ __forceinline__ float warp_red(float v) {
#pragma unroll
    for (int o = 16; o > 0; o >>= 1) v += __shfl_xor_sync(0xffffffffu, v, o);
    return v;
}

// ---------------- kernel 1: fused rmsnorm + QKV GEMV (512 thr, 16 rows/blk, 384 blocks) ----------------
__global__ void __launch_bounds__(512)
k_qkv(const float* __restrict__ x, const float* __restrict__ anw,
      const float* __restrict__ qw, const float* __restrict__ qb,
      const float* __restrict__ kw, const float* __restrict__ kb,
      const float* __restrict__ vw, const float* __restrict__ vb) {
    __shared__ float s_xn[DIM];
    __shared__ float s_red[16];
    __shared__ float s_inv;
    int tid = threadIdx.x, warp = tid >> 5, lane = tid & 31;

    float4 v0 = reinterpret_cast<const float4*>(x)[tid];
    float ss = v0.x*v0.x + v0.y*v0.y + v0.z*v0.z + v0.w*v0.w;
    ss = warp_red(ss);
    if (lane == 0) s_red[warp] = ss;
    __syncthreads();
    if (tid == 0) {
        float t = 0.f;
#pragma unroll
        for (int i = 0; i < 16; i++) t += s_red[i];
        s_inv = rsqrtf(t * (1.f / DIM) + 1e-6f);
    }
    __syncthreads();
    float inv = s_inv;
    float4 n0 = reinterpret_cast<const float4*>(anw)[tid];
    float4* sx4 = reinterpret_cast<float4*>(s_xn);
    sx4[tid] = make_float4(v0.x*inv*n0.x, v0.y*inv*n0.y, v0.z*inv*n0.z, v0.w*inv*n0.w);
    __syncthreads();

    int r = blockIdx.x * 16 + warp;         // 0..6143
    int m = r >> 11, j = r & (DIM - 1);
    const float* W = (m == 0) ? qw : (m == 1) ? kw : vw;
    const float* B = (m == 0) ? qb : (m == 1) ? kb : vb;
    const float4* w4 = reinterpret_cast<const float4*>(W + (size_t)j * DIM);
    float acc = 0.f;
#pragma unroll 16
    for (int i = lane; i < DIM / 4; i += 32) {
        float4 a = __ldcs(&w4[i]); float4 b = sx4[i];
        acc += a.x*b.x + a.y*b.y + a.z*b.z + a.w*b.w;
    }
    acc = warp_red(acc);
    if (lane == 0) g_qkv[r] = acc + B[j];
}

// ---------------- kernel 2: scores -> exp, last block computes 1/Z (512 thr, 16 rows/blk) ----------------
__global__ void __launch_bounds__(512)
k_scores(const float* __restrict__ cacheK, const int* __restrict__ posp) {
    __shared__ float s_q[DIM];
    __shared__ float s_e[16];
    __shared__ float s_z[512];
    __shared__ bool s_last;
    int pos = *posp;
    int tid = threadIdx.x, warp = tid >> 5, lane = tid & 31;
    float4* sq4 = reinterpret_cast<float4*>(s_q);
    sq4[tid] = reinterpret_cast<const float4*>(g_qkv)[tid];
    if (tid < 16) s_e[tid] = 0.f;
    __syncthreads();

    int row = blockIdx.x * 16 + warp;
    if (row <= pos) {
        const float* krow = (row == pos) ? (g_qkv + DIM)
                                         : (cacheK + (size_t)row * DIM);
        const float4* k4 = reinterpret_cast<const float4*>(krow);
        float acc = 0.f;
#pragma unroll 16
        for (int i = lane; i < DIM / 4; i += 32) {
            float4 a = __ldcs(&k4[i]); float4 b = sq4[i];
            acc += a.x*b.x + a.y*b.y + a.z*b.z + a.w*b.w;
        }
        acc = warp_red(acc);
        if (lane == 0) {
            float e = __expf(acc * 0.022097086912079608f);  // 1/sqrt(2048)
            g_probs[row] = e;
            s_e[warp] = e;
        }
    }
    __syncthreads();
    if (tid == 0) {
        float s = 0.f;
#pragma unroll
        for (int i = 0; i < 16; i++) s += s_e[i];
        g_psum[blockIdx.x] = s;
        __threadfence();
        unsigned old = atomicAdd(&g_cnt, 1u);
        s_last = (old == (unsigned)(gridDim.x - 1));
    }
    __syncthreads();
    if (s_last) {
        __threadfence();
        float z = (tid < NSB) ? g_psum[tid] : 0.f;
        if (tid + 512 < NSB) z += g_psum[tid + 512];
        s_z[tid] = z;
        __syncthreads();
        for (int st = 256; st > 0; st >>= 1) {
            if (tid < st) s_z[tid] += s_z[tid + st];
            __syncthreads();
        }
        if (tid == 0) {
            g_invZ = 1.f / s_z[0];
            g_cnt = 0;                       // reset for next graph replay
        }
    }
}

// ---------------- kernel 3: probs @ V, split-K (grid (4,64), 512 thr) ----------------
__global__ void __launch_bounds__(512)
k_attnv(const float* __restrict__ cacheV, const int* __restrict__ posp) {
    int pos = *posp;
    int d = blockIdx.x * 512 + threadIdx.x;
    int s = blockIdx.y;
    float a0 = 0.f, a1 = 0.f, a2 = 0.f, a3 = 0.f;
    int i = s;
    for (; i + 3 * NSPLIT < pos; i += 4 * NSPLIT) {
        a0 += g_probs[i]              * __ldcs(&cacheV[(size_t)i * DIM + d]);
        a1 += g_probs[i + NSPLIT]     * __ldcs(&cacheV[(size_t)(i + NSPLIT) * DIM + d]);
        a2 += g_probs[i + 2 * NSPLIT] * __ldcs(&cacheV[(size_t)(i + 2 * NSPLIT) * DIM + d]);
        a3 += g_probs[i + 3 * NSPLIT] * __ldcs(&cacheV[(size_t)(i + 3 * NSPLIT) * DIM + d]);
    }
    for (; i < pos; i += NSPLIT)
        a0 += g_probs[i] * __ldcs(&cacheV[(size_t)i * DIM + d]);
    if (s == (pos & (NSPLIT - 1)))
        a0 += g_probs[pos] * g_qkv[2 * DIM + d];
    g_partial[(size_t)s * DIM + d] = (a0 + a1) + (a2 + a3);
}

// ---------------- kernel 4: reduce 64 partials (4 thr/dim, MLP=16) + 1/Z ----------------
__global__ void k_attnv_reduce() {
    int tid = threadIdx.x;
    int d = blockIdx.x * 64 + (tid >> 2);
    int q = tid & 3;
    float acc = 0.f;
#pragma unroll
    for (int k = 0; k < NSPLIT / 4; k++)
        acc += g_partial[(size_t)(q + 4 * k) * DIM + d];
    acc += __shfl_xor_sync(0xffffffffu, acc, 1);
    acc += __shfl_xor_sync(0xffffffffu, acc, 2);
    if (q == 0) g_attn[d] = acc * g_invZ;
}

// ---------------- kernel 5: o-proj + residual (512 thr, 16 rows/blk, 128 blocks) ----------------
__global__ void __launch_bounds__(512)
k_oproj(const float* __restrict__ ow, const float* __restrict__ ob,
        const float* __restrict__ x) {
    __shared__ float s_a[DIM];
    int tid = threadIdx.x, warp = tid >> 5, lane = tid & 31;
    float4* sa4 = reinterpret_cast<float4*>(s_a);
    sa4[tid] = reinterpret_cast<const float4*>(g_attn)[tid];
    __syncthreads();

    int row = blockIdx.x * 16 + warp;
    const float4* w4 = reinterpret_cast<const float4*>(ow + (size_t)row * DIM);
    float acc = 0.f;
#pragma unroll 16
    for (int i = lane; i < DIM / 4; i += 32) {
        float4 a = __ldcs(&w4[i]); float4 b = sa4[i];
        acc += a.x*b.x + a.y*b.y + a.z*b.z + a.w*b.w;
    }
    acc = warp_red(acc);
    if (lane == 0) g_x2[row] = x[row] + acc + ob[row];
}

// ---------------- kernel 6: rmsnorm + fc1 + exact GELU (512 thr, 16 rows/blk, 512 blocks) ----------------
__global__ void __launch_bounds__(512)
k_fc1(const float* __restrict__ mnw,
      const float* __restrict__ w1, const float* __restrict__ b1) {
    __shared__ float s_xn[DIM];
    __shared__ float s_red[16];
    __shared__ float s_inv;
    int tid = threadIdx.x, warp = tid >> 5, lane = tid & 31;

    float4 v0 = reinterpret_cast<const float4*>(g_x2)[tid];
    float ss = v0.x*v0.x + v0.y*v0.y + v0.z*v0.z + v0.w*v0.w;
    ss = warp_red(ss);
    if (lane == 0) s_red[warp] = ss;
    __syncthreads();
    if (tid == 0) {
        float t = 0.f;
#pragma unroll
        for (int i = 0; i < 16; i++) t += s_red[i];
        s_inv = rsqrtf(t * (1.f / DIM) + 1e-6f);
    }
    __syncthreads();
    float inv = s_inv;
    float4 n0 = reinterpret_cast<const float4*>(mnw)[tid];
    float4* sx4 = reinterpret_cast<float4*>(s_xn);
    sx4[tid] = make_float4(v0.x*inv*n0.x, v0.y*inv*n0.y, v0.z*inv*n0.z, v0.w*inv*n0.w);
    __syncthreads();

    int row = blockIdx.x * 16 + warp;       // 0..8191
    const float4* w4 = reinterpret_cast<const float4*>(w1 + (size_t)row * DIM);
    float acc = 0.f;
#pragma unroll 16
    for (int i = lane; i < DIM / 4; i += 32) {
        float4 a = __ldcs(&w4[i]); float4 b = sx4[i];
        acc += a.x*b.x + a.y*b.y + a.z*b.z + a.w*b.w;
    }
    acc = warp_red(acc);
    if (lane == 0) {
        float u = acc + b1[row];
        g_h[row] = 0.5f * u * (1.f + erff(u * 0.70710678118654752f));
    }
}

// ---------------- kernel 7: fc2 + residual -> out (512 thr, 8 rows/blk, 2 warps/row, 256 blocks) ----------------
__global__ void __launch_bounds__(512)
k_fc2(const float* __restrict__ w2, const float* __restrict__ b2,
      float* __restrict__ out) {
    __shared__ float s_h[HID];
    __shared__ float s_part[8][2];
    int tid = threadIdx.x, warp = tid >> 5, lane = tid & 31;
    float4* sh4 = reinterpret_cast<float4*>(s_h);
    const float4* h4 = reinterpret_cast<const float4*>(g_h);
#pragma unroll
    for (int i = 0; i < 4; i++) sh4[tid + 512 * i] = h4[tid + 512 * i];
    __syncthreads();

    int rl = warp >> 1, half = warp & 1;
    int row = blockIdx.x * 8 + rl;
    const float4* w4 = reinterpret_cast<const float4*>(w2 + (size_t)row * HID);
    float acc = 0.f;
    int base = half * 1024;
#pragma unroll 16
    for (int i = base + lane; i < base + 1024; i += 32) {
        float4 a = __ldcs(&w4[i]); float4 b = sh4[i];
        acc += a.x*b.x + a.y*b.y + a.z*b.z + a.w*b.w;
    }
    acc = warp_red(acc);
    if (lane == 0) s_part[rl][half] = acc;
    __syncthreads();
    if (tid < 8) {
        int r = blockIdx.x * 8 + tid;
        out[r] = g_x2[r] + s_part[tid][0] + s_part[tid][1] + b2[r];
    }
}

// ---------------- launch ----------------
extern "C" void kernel_launch(void* const* d_in, const int* in_sizes, int n_in,
                              void* d_out, int out_size) {
    const float* x      = (const float*)d_in[0];
    const float* cacheK = (const float*)d_in[1];
    const float* cacheV = (const float*)d_in[2];
    const float* anw    = (const float*)d_in[3];
    const float* qw     = (const float*)d_in[4];
    const float* qb     = (const float*)d_in[5];
    const float* kw     = (const float*)d_in[6];
    const float* kb     = (const float*)d_in[7];
    const float* vw     = (const float*)d_in[8];
    const float* vb     = (const float*)d_in[9];
    const float* ow     = (const float*)d_in[10];
    const float* ob     = (const float*)d_in[11];
    const float* mnw    = (const float*)d_in[12];
    const float* w1     = (const float*)d_in[13];
    const float* b1     = (const float*)d_in[14];
    const float* w2     = (const float*)d_in[15];
    const float* b2     = (const float*)d_in[16];
    const int*   posp   = (const int*)d_in[17];
    float* out = (float*)d_out;

    k_qkv<<<(3 * DIM) / 16, 512>>>(x, anw, qw, qb, kw, kb, vw, vb);
    k_scores<<<NSB, 512>>>(cacheK, posp);
    k_attnv<<<dim3(DIM / 512, NSPLIT), 512>>>(cacheV, posp);
    k_attnv_reduce<<<DIM / 64, 256>>>();
    k_oproj<<<DIM / 16, 512>>>(ow, ob, x);
    k_fc1<<<HID / 16, 512>>>(mnw, w1, b1);
    k_fc2<<<DIM / 8, 512>>>(w2, b2, out);
}